// round 16
// baseline (speedup 1.0000x reference)
#include <cuda_runtime.h>
#include <cuda_bf16.h>
#include <cstdint>

// ============================================================================
// Fused dopri5 neural-ODE via mma.sync bf16 (sm_103-safe HMMA path).
// fp32 = bf16 hi/lo split, 3 products.
// R15 (= R14 minimal-traffic tiling + explicit latency hiding):
//   128 CTAs x 32 rows, 256 thr / 8 warps, warp = m32 x n32.
//   B: GLOBAL fragment image -> registers, prefetch distance 2 (3 buffers).
//   A: smem ldsm, register double-buffer (kstep+1 loaded ahead).
//   x/xacc state in smem [frag][tid] (frees 64 regs for the buffers).
// ============================================================================

#define THREADS   256
#define NWARP     8
#define NSTEPS    40
#define DIM       256
#define BROWS     4096
#define M_CTA     32
#define NCTA      (BROWS / M_CTA)        // 128
#define NGEMM     (NSTEPS * 6 * 2)       // 480
#define NKSTEP    (NGEMM * 16)           // 7680 k16-steps

#define LDA       264                    // A row stride (elements)
#define ABUF_B    (M_CTA * LDA * 2 * 2)  // 33792 per buffer (hi+lo planes)
#define A_LO      (M_CTA * LDA * 2)      // 16896
#define XREG_OFF  (2 * ABUF_B)           // 67584
#define XACC_OFF  (XREG_OFF + 32768)     // 100352
#define SMEM_BYTES (XACC_OFF + 32768)    // 133120

#define FRAG_CTA  (M_CTA * DIM)          // 8192 floats per CTA

// W fragment image (512KB, L2-resident). combo = (((wi*8+ns)*8+sub)*2+kq)*2+plane
__device__ uint32_t g_wfrag[131072];
__device__ float g_k[4][BROWS * DIM];    // k1..k4, fragment layout

__constant__ float c_cur[6] = {
    (float)(0.025 * 0.2), (float)(0.025 * 9.0 / 40.0), (float)(0.025 * 32.0 / 9.0),
    (float)(0.025 * -212.0 / 729.0), (float)(0.025 * -5103.0 / 18656.0),
    (float)(0.025 * 11.0 / 84.0)};
__constant__ float c_slot[5][4] = {
    {0.f, 0.f, 0.f, 0.f},
    {(float)(0.025 * 3.0 / 40.0), 0.f, 0.f, 0.f},
    {(float)(0.025 * 44.0 / 45.0), (float)(0.025 * -56.0 / 15.0), 0.f, 0.f},
    {(float)(0.025 * 19372.0 / 6561.0), (float)(0.025 * -25360.0 / 2187.0),
     (float)(0.025 * 64448.0 / 6561.0), 0.f},
    {(float)(0.025 * 9017.0 / 3168.0), (float)(0.025 * -355.0 / 33.0),
     (float)(0.025 * 46732.0 / 5247.0), (float)(0.025 * 49.0 / 176.0)}};
__constant__ float c_b[6] = {
    (float)(0.025 * 35.0 / 384.0), 0.f, (float)(0.025 * 500.0 / 1113.0),
    (float)(0.025 * 125.0 / 192.0), (float)(0.025 * -2187.0 / 6784.0), 0.f};

__device__ __forceinline__ uint32_t smem_u32(const void* p) {
    uint32_t a;
    asm("{ .reg .u64 t; cvta.to.shared.u64 t, %1; cvt.u32.u64 %0, t; }" : "=r"(a) : "l"(p));
    return a;
}
__device__ __forceinline__ void ldsm_x4(uint32_t* r, uint32_t addr) {
    asm volatile("ldmatrix.sync.aligned.m8n8.x4.shared.b16 {%0,%1,%2,%3}, [%4];"
                 : "=r"(r[0]), "=r"(r[1]), "=r"(r[2]), "=r"(r[3]) : "r"(addr));
}
__device__ __forceinline__ void mma_bf16(float* c, const uint32_t* a, const uint32_t* b) {
    asm volatile("mma.sync.aligned.m16n8k16.row.col.f32.bf16.bf16.f32 "
                 "{%0,%1,%2,%3}, {%4,%5,%6,%7}, {%8,%9}, {%0,%1,%2,%3};"
                 : "+f"(c[0]), "+f"(c[1]), "+f"(c[2]), "+f"(c[3])
                 : "r"(a[0]), "r"(a[1]), "r"(a[2]), "r"(a[3]), "r"(b[0]), "r"(b[1]));
}

__device__ __forceinline__ float tanh_f(float x) {
    float ax = fabsf(x);
    float e  = __expf(2.0f * ax);
    float r  = __fdividef(2.0f, e + 1.0f);
    return copysignf(1.0f - r, x);
}
__device__ __forceinline__ uint32_t bpack(float a, float b) {
    __nv_bfloat162 h = __floats2bfloat162_rn(a, b);
    return *(uint32_t*)&h;
}
__device__ __forceinline__ void writeA(uint32_t sb, int buf, int row, int col,
                                       float a, float b) {
    float ah = __bfloat162float(__float2bfloat16(a));
    float bh = __bfloat162float(__float2bfloat16(b));
    uint32_t off = sb + (uint32_t)buf * ABUF_B + (uint32_t)(row * LDA + col) * 2;
    asm volatile("st.shared.b32 [%0], %1;" :: "r"(off), "r"(bpack(ah, bh)) : "memory");
    asm volatile("st.shared.b32 [%0], %1;" :: "r"(off + A_LO), "r"(bpack(a - ah, b - bh)) : "memory");
}
__device__ __forceinline__ void sts_f4(uint32_t addr, float4 v) {
    asm volatile("st.shared.v4.b32 [%0], {%1,%2,%3,%4};"
                 :: "r"(addr), "r"(__float_as_uint(v.x)), "r"(__float_as_uint(v.y)),
                    "r"(__float_as_uint(v.z)), "r"(__float_as_uint(v.w)) : "memory");
}
__device__ __forceinline__ float4 lds_f4(uint32_t addr) {
    uint32_t a, b, c, d;
    asm volatile("ld.shared.v4.b32 {%0,%1,%2,%3}, [%4];"
                 : "=r"(a), "=r"(b), "=r"(c), "=r"(d) : "r"(addr));
    return make_float4(__uint_as_float(a), __uint_as_float(b),
                       __uint_as_float(c), __uint_as_float(d));
}

// prep: W -> fragment-order image (unchanged from R13/R14).
__global__ void prep_kernel(const float* __restrict__ W1, const float* __restrict__ W2) {
    int i = blockIdx.x * blockDim.x + threadIdx.x;   // 0..131071
    int rr = i & 3, lane = (i >> 2) & 31, h = (i >> 7) & 1;
    int plane = (i >> 8) & 1, kq = (i >> 9) & 1, sub = (i >> 10) & 7;
    int ns = (i >> 13) & 7, wi = (i >> 16) & 1;
    int r = h * 4 + rr, f = r >> 1;
    int n = ns * 32 + f * 8 + (lane >> 2);
    int k = sub * 32 + kq * 16 + (r & 1) * 8 + 2 * (lane & 3);
    const float* W = wi ? W2 : W1;
    float v0 = W[k * 256 + n], v1 = W[(k + 1) * 256 + n];
    __nv_bfloat16 h0 = __float2bfloat16(v0), h1 = __float2bfloat16(v1);
    uint32_t outv;
    if (plane == 0) {
        outv = ((uint32_t)__bfloat16_as_ushort(h1) << 16) | __bfloat16_as_ushort(h0);
    } else {
        __nv_bfloat16 l0 = __float2bfloat16(v0 - __bfloat162float(h0));
        __nv_bfloat16 l1 = __float2bfloat16(v1 - __bfloat162float(h1));
        outv = ((uint32_t)__bfloat16_as_ushort(l1) << 16) | __bfloat16_as_ushort(l0);
    }
    int combo = ((((wi * 8 + ns) * 8 + sub) * 2 + kq) * 2 + plane);
    g_wfrag[combo * 256 + (h * 32 + lane) * 4 + rr] = outv;
}

// B frags for one k16-step: hi[0..7] + lo[0..7] (16 regs)
__device__ __forceinline__ void ldw(int step, int ns, int lane, uint32_t* dst) {
    const int wi = (step >> 4) & 1, sub = (step >> 1) & 7, kq = step & 1;
    const uint4* p = (const uint4*)g_wfrag +
                     (size_t)((((wi * 8 + ns) * 8 + sub) * 2 + kq) * 2) * 64 + lane;
    uint4 t0 = p[0], t1 = p[32];     // plane 0 (hi)
    uint4 t2 = p[64], t3 = p[96];    // plane 1 (lo)
    dst[0] = t0.x; dst[1] = t0.y; dst[2]  = t0.z; dst[3]  = t0.w;
    dst[4] = t1.x; dst[5] = t1.y; dst[6]  = t1.z; dst[7]  = t1.w;
    dst[8] = t2.x; dst[9] = t2.y; dst[10] = t2.z; dst[11] = t2.w;
    dst[12] = t3.x; dst[13] = t3.y; dst[14] = t3.z; dst[15] = t3.w;
}

// A frags (both mi, hi+lo) for one k16-step: 16 regs
__device__ __forceinline__ void ldA(uint32_t abase, int ks, int a_row, int a_col8,
                                    uint32_t* dst) {
#pragma unroll
    for (int mi = 0; mi < 2; mi++) {
        uint32_t ao = abase + (uint32_t)(((mi * 16 + a_row) * LDA + ks * 16 + a_col8) * 2);
        ldsm_x4(dst + mi * 8, ao);
        ldsm_x4(dst + mi * 8 + 4, ao + A_LO);
    }
}

__global__ void __launch_bounds__(THREADS, 1)
ode_hmma_kernel(const float* __restrict__ x0, float* __restrict__ out) {
    extern __shared__ __align__(16) char smem[];
    const uint32_t sb = smem_u32(smem);
    const int tid = threadIdx.x, warp = tid >> 5, lane = tid & 31;
    const int quad = lane >> 3, lrow = lane & 7;

    const int a_row  = lrow + ((quad & 1) << 3);
    const int a_col8 = (quad >> 1) << 3;

    const int erow = lane >> 2;
    const int ecol = warp * 32 + 2 * (lane & 3);     // + ni*8
    const int fbase = blockIdx.x * FRAG_CTA + warp * 1024 + lane * 4;
    const int growb = blockIdx.x * M_CTA;
    const uint32_t xr0 = sb + XREG_OFF + (uint32_t)tid * 16;   // + idx*4096
    const uint32_t xa0 = sb + XACC_OFF + (uint32_t)tid * 16;

    // ---- init: x0 -> xreg smem and A buffer 0 ----
#pragma unroll
    for (int mi = 0; mi < 2; mi++)
#pragma unroll
        for (int ni = 0; ni < 4; ni++) {
            int row = mi * 16 + erow, col = ecol + ni * 8;
            float2 v01 = *(const float2*)&x0[(growb + row) * DIM + col];
            float2 v23 = *(const float2*)&x0[(growb + row + 8) * DIM + col];
            sts_f4(xr0 + (uint32_t)(mi * 4 + ni) * 4096,
                   make_float4(v01.x, v01.y, v23.x, v23.y));
            writeA(sb, 0, row, col, v01.x, v01.y);
            writeA(sb, 0, row + 8, col, v23.x, v23.y);
        }

    uint32_t bw[3][16];
    ldw(0, warp, lane, bw[0]);
    ldw(1, warp, lane, bw[1]);

    __syncthreads();

    uint32_t areg[2][16];
    float accA[2][4][4], accB[2][4][4];
#pragma unroll 1
    for (int g = 0; g < NGEMM; g++) {
        const int s = (g >> 1) % 6, j = g & 1;
        const uint32_t abase = sb + (uint32_t)(g & 1) * ABUF_B;
#pragma unroll
        for (int mi = 0; mi < 2; mi++)
#pragma unroll
            for (int ni = 0; ni < 4; ni++)
#pragma unroll
                for (int c = 0; c < 4; c++) {
                    accA[mi][ni][c] = 0.0f;
                    accB[mi][ni][c] = 0.0f;
                }

        ldA(abase, 0, a_row, a_col8, areg[0]);       // A kstep 0

#pragma unroll 2
        for (int ks = 0; ks < 16; ks++) {
            const int step = g * 16 + ks;
            if (step + 2 < NKSTEP)                   // B distance-2 prefetch
                ldw(step + 2, warp, lane, bw[(step + 2) % 3]);
            if (ks < 15)                             // A next-kstep prefetch
                ldA(abase, ks + 1, a_row, a_col8, areg[(ks + 1) & 1]);
            const uint32_t* bb  = bw[step % 3];
            const uint32_t* bhi = bb;
            const uint32_t* blo = bb + 8;
            const uint32_t* aa  = areg[ks & 1];
#pragma unroll
            for (int mi = 0; mi < 2; mi++) {
                const uint32_t* ahi = aa + mi * 8;
                const uint32_t* alo = ahi + 4;
#pragma unroll
                for (int ni = 0; ni < 4; ni++) {
                    mma_bf16(accA[mi][ni], ahi, &bhi[ni * 2]);  // hi*hi
                    mma_bf16(accB[mi][ni], alo, &bhi[ni * 2]);  // lo*hi
                    mma_bf16(accB[mi][ni], ahi, &blo[ni * 2]);  // hi*lo
                }
            }
        }

        // ---- epilogue -> A buffer (g+1)&1 ----
        const int nbuf = (g + 1) & 1;
        if (j == 0) {                      // h = tanh(x@W1)
#pragma unroll
            for (int mi = 0; mi < 2; mi++)
#pragma unroll
                for (int ni = 0; ni < 4; ni++) {
                    float a0 = accA[mi][ni][0] + accB[mi][ni][0];
                    float a1 = accA[mi][ni][1] + accB[mi][ni][1];
                    float a2 = accA[mi][ni][2] + accB[mi][ni][2];
                    float a3 = accA[mi][ni][3] + accB[mi][ni][3];
                    int row = mi * 16 + erow, col = ecol + ni * 8;
                    writeA(sb, nbuf, row, col, tanh_f(a0), tanh_f(a1));
                    writeA(sb, nbuf, row + 8, col, tanh_f(a2), tanh_f(a3));
                }
        } else {                           // k_{s+1} = h@W2; RK update
            const bool fin = (s == 5);
            const float cc = c_cur[s];
            const float cb = c_b[s];
#pragma unroll
            for (int mi = 0; mi < 2; mi++)
#pragma unroll
                for (int ni = 0; ni < 4; ni++) {
                    const int idx = mi * 4 + ni;
                    const int fi = fbase + idx * 128;
                    const uint32_t xraddr = xr0 + (uint32_t)idx * 4096;
                    const uint32_t xaaddr = xa0 + (uint32_t)idx * 4096;
                    float4 kc = make_float4(accA[mi][ni][0] + accB[mi][ni][0],
                                            accA[mi][ni][1] + accB[mi][ni][1],
                                            accA[mi][ni][2] + accB[mi][ni][2],
                                            accA[mi][ni][3] + accB[mi][ni][3]);
                    if (s <= 3) *(float4*)&g_k[s][fi] = kc;
                    float4 xv = lds_f4(xraddr);
                    if (s == 0) {
                        sts_f4(xaaddr, make_float4(fmaf(cb, kc.x, xv.x), fmaf(cb, kc.y, xv.y),
                                                   fmaf(cb, kc.z, xv.z), fmaf(cb, kc.w, xv.w)));
                    } else if (cb != 0.0f) {
                        float4 t = lds_f4(xaaddr);
                        sts_f4(xaaddr, make_float4(fmaf(cb, kc.x, t.x), fmaf(cb, kc.y, t.y),
                                                   fmaf(cb, kc.z, t.z), fmaf(cb, kc.w, t.w)));
                    }
                    float4 na;
                    if (!fin) {            // y_{s+2} = x + cc*k_cur + sum_{sl<s}
                        na = make_float4(fmaf(cc, kc.x, xv.x), fmaf(cc, kc.y, xv.y),
                                         fmaf(cc, kc.z, xv.z), fmaf(cc, kc.w, xv.w));
                        float4 kv[4];
#pragma unroll
                        for (int sl = 0; sl < 4; sl++)
                            if (sl < s) kv[sl] = *(const float4*)&g_k[sl][fi];
#pragma unroll
                        for (int sl = 0; sl < 4; sl++)
                            if (sl < s) {
                                float cf = c_slot[s][sl];
                                na.x = fmaf(cf, kv[sl].x, na.x);
                                na.y = fmaf(cf, kv[sl].y, na.y);
                                na.z = fmaf(cf, kv[sl].z, na.z);
                                na.w = fmaf(cf, kv[sl].w, na.w);
                            }
                    } else {               // new x = xacc + h*b6*k6
                        float4 t = lds_f4(xaaddr);
                        na = make_float4(fmaf(cc, kc.x, t.x), fmaf(cc, kc.y, t.y),
                                         fmaf(cc, kc.z, t.z), fmaf(cc, kc.w, t.w));
                        sts_f4(xraddr, na);            // new x state
                    }
                    int row = mi * 16 + erow, col = ecol + ni * 8;
                    if (g == NGEMM - 1) {
                        *(float2*)&out[(growb + row) * DIM + col] = make_float2(na.x, na.y);
                        *(float2*)&out[(growb + row + 8) * DIM + col] = make_float2(na.z, na.w);
                    } else {
                        writeA(sb, nbuf, row, col, na.x, na.y);
                        writeA(sb, nbuf, row + 8, col, na.z, na.w);
                    }
                }
        }
        __syncthreads();   // publish A buffer (g+1)&1
    }
}

extern "C" void kernel_launch(void* const* d_in, const int* in_sizes, int n_in,
                              void* d_out, int out_size) {
    (void)in_sizes; (void)n_in; (void)out_size;
    const float* x0 = (const float*)d_in[0];
    const float* W1 = (const float*)d_in[1];
    const float* W2 = (const float*)d_in[2];
    float* out = (float*)d_out;

    prep_kernel<<<512, 256>>>(W1, W2);
    cudaFuncSetAttribute(ode_hmma_kernel,
                         cudaFuncAttributeMaxDynamicSharedMemorySize, SMEM_BYTES);
    ode_hmma_kernel<<<NCTA, THREADS, SMEM_BYTES>>>(x0, out);
}

// round 17
// speedup vs baseline: 2.0616x; 2.0616x over previous
#include <cuda_runtime.h>
#include <cuda_bf16.h>
#include <cstdint>

// ============================================================================
// Fused dopri5 neural-ODE via mma.sync bf16 (sm_103-safe HMMA path).
// fp32 = bf16 hi/lo split, 3 products.
// R16 = R14 minimal-traffic tiling (128 CTAs x 32 rows, 8 warps, warp=m32xn32)
// with STATIC-INDEX latency hiding (R15's bug was bw[step%3] -> local mem):
//   B: 4-slot register ring indexed ks&3 (compile-time under unroll 4),
//      prefetch distance 2 (~360cyc > L2 262).
//   A: 2-slot register ring indexed (ks+1)&1, next-kstep prefetch.
//   x/xacc in smem [frag][tid]; dual accumulators kept.
// ============================================================================

#define THREADS   256
#define NWARP     8
#define NSTEPS    40
#define DIM       256
#define BROWS     4096
#define M_CTA     32
#define NCTA      (BROWS / M_CTA)        // 128
#define NGEMM     (NSTEPS * 6 * 2)       // 480
#define NKSTEP    (NGEMM * 16)           // 7680 k16-steps

#define LDA       264                    // A row stride (elements)
#define ABUF_B    (M_CTA * LDA * 2 * 2)  // 33792 per buffer (hi+lo planes)
#define A_LO      (M_CTA * LDA * 2)      // 16896
#define XREG_OFF  (2 * ABUF_B)           // 67584
#define XACC_OFF  (XREG_OFF + 32768)     // 100352
#define SMEM_BYTES (XACC_OFF + 32768)    // 133120

#define FRAG_CTA  (M_CTA * DIM)          // 8192 floats per CTA

// W fragment image (512KB, L2-resident). combo = (((wi*8+ns)*8+sub)*2+kq)*2+plane
__device__ uint32_t g_wfrag[131072];
__device__ float g_k[4][BROWS * DIM];    // k1..k4, fragment layout

__constant__ float c_cur[6] = {
    (float)(0.025 * 0.2), (float)(0.025 * 9.0 / 40.0), (float)(0.025 * 32.0 / 9.0),
    (float)(0.025 * -212.0 / 729.0), (float)(0.025 * -5103.0 / 18656.0),
    (float)(0.025 * 11.0 / 84.0)};
__constant__ float c_slot[5][4] = {
    {0.f, 0.f, 0.f, 0.f},
    {(float)(0.025 * 3.0 / 40.0), 0.f, 0.f, 0.f},
    {(float)(0.025 * 44.0 / 45.0), (float)(0.025 * -56.0 / 15.0), 0.f, 0.f},
    {(float)(0.025 * 19372.0 / 6561.0), (float)(0.025 * -25360.0 / 2187.0),
     (float)(0.025 * 64448.0 / 6561.0), 0.f},
    {(float)(0.025 * 9017.0 / 3168.0), (float)(0.025 * -355.0 / 33.0),
     (float)(0.025 * 46732.0 / 5247.0), (float)(0.025 * 49.0 / 176.0)}};
__constant__ float c_b[6] = {
    (float)(0.025 * 35.0 / 384.0), 0.f, (float)(0.025 * 500.0 / 1113.0),
    (float)(0.025 * 125.0 / 192.0), (float)(0.025 * -2187.0 / 6784.0), 0.f};

__device__ __forceinline__ uint32_t smem_u32(const void* p) {
    uint32_t a;
    asm("{ .reg .u64 t; cvta.to.shared.u64 t, %1; cvt.u32.u64 %0, t; }" : "=r"(a) : "l"(p));
    return a;
}
__device__ __forceinline__ void ldsm_x4(uint32_t* r, uint32_t addr) {
    asm volatile("ldmatrix.sync.aligned.m8n8.x4.shared.b16 {%0,%1,%2,%3}, [%4];"
                 : "=r"(r[0]), "=r"(r[1]), "=r"(r[2]), "=r"(r[3]) : "r"(addr));
}
__device__ __forceinline__ void mma_bf16(float* c, const uint32_t* a, const uint32_t* b) {
    asm volatile("mma.sync.aligned.m16n8k16.row.col.f32.bf16.bf16.f32 "
                 "{%0,%1,%2,%3}, {%4,%5,%6,%7}, {%8,%9}, {%0,%1,%2,%3};"
                 : "+f"(c[0]), "+f"(c[1]), "+f"(c[2]), "+f"(c[3])
                 : "r"(a[0]), "r"(a[1]), "r"(a[2]), "r"(a[3]), "r"(b[0]), "r"(b[1]));
}

__device__ __forceinline__ float tanh_f(float x) {
    float ax = fabsf(x);
    float e  = __expf(2.0f * ax);
    float r  = __fdividef(2.0f, e + 1.0f);
    return copysignf(1.0f - r, x);
}
__device__ __forceinline__ uint32_t bpack(float a, float b) {
    __nv_bfloat162 h = __floats2bfloat162_rn(a, b);
    return *(uint32_t*)&h;
}
__device__ __forceinline__ void writeA(uint32_t sb, int buf, int row, int col,
                                       float a, float b) {
    float ah = __bfloat162float(__float2bfloat16(a));
    float bh = __bfloat162float(__float2bfloat16(b));
    uint32_t off = sb + (uint32_t)buf * ABUF_B + (uint32_t)(row * LDA + col) * 2;
    asm volatile("st.shared.b32 [%0], %1;" :: "r"(off), "r"(bpack(ah, bh)) : "memory");
    asm volatile("st.shared.b32 [%0], %1;" :: "r"(off + A_LO), "r"(bpack(a - ah, b - bh)) : "memory");
}
__device__ __forceinline__ void sts_f4(uint32_t addr, float4 v) {
    asm volatile("st.shared.v4.b32 [%0], {%1,%2,%3,%4};"
                 :: "r"(addr), "r"(__float_as_uint(v.x)), "r"(__float_as_uint(v.y)),
                    "r"(__float_as_uint(v.z)), "r"(__float_as_uint(v.w)) : "memory");
}
__device__ __forceinline__ float4 lds_f4(uint32_t addr) {
    uint32_t a, b, c, d;
    asm volatile("ld.shared.v4.b32 {%0,%1,%2,%3}, [%4];"
                 : "=r"(a), "=r"(b), "=r"(c), "=r"(d) : "r"(addr));
    return make_float4(__uint_as_float(a), __uint_as_float(b),
                       __uint_as_float(c), __uint_as_float(d));
}

// prep: W -> fragment-order image (unchanged).
__global__ void prep_kernel(const float* __restrict__ W1, const float* __restrict__ W2) {
    int i = blockIdx.x * blockDim.x + threadIdx.x;   // 0..131071
    int rr = i & 3, lane = (i >> 2) & 31, h = (i >> 7) & 1;
    int plane = (i >> 8) & 1, kq = (i >> 9) & 1, sub = (i >> 10) & 7;
    int ns = (i >> 13) & 7, wi = (i >> 16) & 1;
    int r = h * 4 + rr, f = r >> 1;
    int n = ns * 32 + f * 8 + (lane >> 2);
    int k = sub * 32 + kq * 16 + (r & 1) * 8 + 2 * (lane & 3);
    const float* W = wi ? W2 : W1;
    float v0 = W[k * 256 + n], v1 = W[(k + 1) * 256 + n];
    __nv_bfloat16 h0 = __float2bfloat16(v0), h1 = __float2bfloat16(v1);
    uint32_t outv;
    if (plane == 0) {
        outv = ((uint32_t)__bfloat16_as_ushort(h1) << 16) | __bfloat16_as_ushort(h0);
    } else {
        __nv_bfloat16 l0 = __float2bfloat16(v0 - __bfloat162float(h0));
        __nv_bfloat16 l1 = __float2bfloat16(v1 - __bfloat162float(h1));
        outv = ((uint32_t)__bfloat16_as_ushort(l1) << 16) | __bfloat16_as_ushort(l0);
    }
    int combo = ((((wi * 8 + ns) * 8 + sub) * 2 + kq) * 2 + plane);
    g_wfrag[combo * 256 + (h * 32 + lane) * 4 + rr] = outv;
}

// B frags for one k16-step: hi[0..7] + lo[0..7] (16 regs)
__device__ __forceinline__ void ldw(int step, int ns, int lane, uint32_t* dst) {
    const int wi = (step >> 4) & 1, sub = (step >> 1) & 7, kq = step & 1;
    const uint4* p = (const uint4*)g_wfrag +
                     (size_t)((((wi * 8 + ns) * 8 + sub) * 2 + kq) * 2) * 64 + lane;
    uint4 t0 = p[0], t1 = p[32];     // plane 0 (hi)
    uint4 t2 = p[64], t3 = p[96];    // plane 1 (lo)
    dst[0] = t0.x; dst[1] = t0.y; dst[2]  = t0.z; dst[3]  = t0.w;
    dst[4] = t1.x; dst[5] = t1.y; dst[6]  = t1.z; dst[7]  = t1.w;
    dst[8] = t2.x; dst[9] = t2.y; dst[10] = t2.z; dst[11] = t2.w;
    dst[12] = t3.x; dst[13] = t3.y; dst[14] = t3.z; dst[15] = t3.w;
}

// A frags (both mi, hi+lo) for one k16-step: 16 regs
__device__ __forceinline__ void ldA(uint32_t abase, int ks, int a_row, int a_col8,
                                    uint32_t* dst) {
#pragma unroll
    for (int mi = 0; mi < 2; mi++) {
        uint32_t ao = abase + (uint32_t)(((mi * 16 + a_row) * LDA + ks * 16 + a_col8) * 2);
        ldsm_x4(dst + mi * 8, ao);
        ldsm_x4(dst + mi * 8 + 4, ao + A_LO);
    }
}

__global__ void __launch_bounds__(THREADS, 1)
ode_hmma_kernel(const float* __restrict__ x0, float* __restrict__ out) {
    extern __shared__ __align__(16) char smem[];
    const uint32_t sb = smem_u32(smem);
    const int tid = threadIdx.x, warp = tid >> 5, lane = tid & 31;
    const int quad = lane >> 3, lrow = lane & 7;

    const int a_row  = lrow + ((quad & 1) << 3);
    const int a_col8 = (quad >> 1) << 3;

    const int erow = lane >> 2;
    const int ecol = warp * 32 + 2 * (lane & 3);     // + ni*8
    const int fbase = blockIdx.x * FRAG_CTA + warp * 1024 + lane * 4;
    const int growb = blockIdx.x * M_CTA;
    const uint32_t xr0 = sb + XREG_OFF + (uint32_t)tid * 16;   // + idx*4096
    const uint32_t xa0 = sb + XACC_OFF + (uint32_t)tid * 16;

    // ---- init: x0 -> xreg smem and A buffer 0 ----
#pragma unroll
    for (int mi = 0; mi < 2; mi++)
#pragma unroll
        for (int ni = 0; ni < 4; ni++) {
            int row = mi * 16 + erow, col = ecol + ni * 8;
            float2 v01 = *(const float2*)&x0[(growb + row) * DIM + col];
            float2 v23 = *(const float2*)&x0[(growb + row + 8) * DIM + col];
            sts_f4(xr0 + (uint32_t)(mi * 4 + ni) * 4096,
                   make_float4(v01.x, v01.y, v23.x, v23.y));
            writeA(sb, 0, row, col, v01.x, v01.y);
            writeA(sb, 0, row + 8, col, v23.x, v23.y);
        }

    // B ring: 4 slots, slot = step&3 = ks&3 (g*16 is a multiple of 4).
    uint32_t bw[4][16];
    ldw(0, warp, lane, bw[0]);
    ldw(1, warp, lane, bw[1]);

    __syncthreads();

    uint32_t areg[2][16];
    float accA[2][4][4], accB[2][4][4];
#pragma unroll 1
    for (int g = 0; g < NGEMM; g++) {
        const int s = (g >> 1) % 6, j = g & 1;
        const uint32_t abase = sb + (uint32_t)(g & 1) * ABUF_B;
#pragma unroll
        for (int mi = 0; mi < 2; mi++)
#pragma unroll
            for (int ni = 0; ni < 4; ni++)
#pragma unroll
                for (int c = 0; c < 4; c++) {
                    accA[mi][ni][c] = 0.0f;
                    accB[mi][ni][c] = 0.0f;
                }

        ldA(abase, 0, a_row, a_col8, areg[0]);       // A kstep 0

#pragma unroll 4
        for (int ks = 0; ks < 16; ks++) {
            const int step = g * 16 + ks;
            if (step + 2 < NKSTEP)                   // B distance-2 prefetch
                ldw(step + 2, warp, lane, bw[(ks + 2) & 3]);  // static index!
            if (ks < 15)                             // A next-kstep prefetch
                ldA(abase, ks + 1, a_row, a_col8, areg[(ks + 1) & 1]);
            const uint32_t* bb  = bw[ks & 3];
            const uint32_t* bhi = bb;
            const uint32_t* blo = bb + 8;
            const uint32_t* aa  = areg[ks & 1];
#pragma unroll
            for (int mi = 0; mi < 2; mi++) {
                const uint32_t* ahi = aa + mi * 8;
                const uint32_t* alo = ahi + 4;
#pragma unroll
                for (int ni = 0; ni < 4; ni++) {
                    mma_bf16(accA[mi][ni], ahi, &bhi[ni * 2]);  // hi*hi
                    mma_bf16(accB[mi][ni], alo, &bhi[ni * 2]);  // lo*hi
                    mma_bf16(accB[mi][ni], ahi, &blo[ni * 2]);  // hi*lo
                }
            }
        }

        // ---- epilogue -> A buffer (g+1)&1 ----
        const int nbuf = (g + 1) & 1;
        if (j == 0) {                      // h = tanh(x@W1)
#pragma unroll
            for (int mi = 0; mi < 2; mi++)
#pragma unroll
                for (int ni = 0; ni < 4; ni++) {
                    float a0 = accA[mi][ni][0] + accB[mi][ni][0];
                    float a1 = accA[mi][ni][1] + accB[mi][ni][1];
                    float a2 = accA[mi][ni][2] + accB[mi][ni][2];
                    float a3 = accA[mi][ni][3] + accB[mi][ni][3];
                    int row = mi * 16 + erow, col = ecol + ni * 8;
                    writeA(sb, nbuf, row, col, tanh_f(a0), tanh_f(a1));
                    writeA(sb, nbuf, row + 8, col, tanh_f(a2), tanh_f(a3));
                }
        } else {                           // k_{s+1} = h@W2; RK update
            const bool fin = (s == 5);
            const float cc = c_cur[s];
            const float cb = c_b[s];
#pragma unroll
            for (int mi = 0; mi < 2; mi++)
#pragma unroll
                for (int ni = 0; ni < 4; ni++) {
                    const int idx = mi * 4 + ni;
                    const int fi = fbase + idx * 128;
                    const uint32_t xraddr = xr0 + (uint32_t)idx * 4096;
                    const uint32_t xaaddr = xa0 + (uint32_t)idx * 4096;
                    float4 kc = make_float4(accA[mi][ni][0] + accB[mi][ni][0],
                                            accA[mi][ni][1] + accB[mi][ni][1],
                                            accA[mi][ni][2] + accB[mi][ni][2],
                                            accA[mi][ni][3] + accB[mi][ni][3]);
                    if (s <= 3) *(float4*)&g_k[s][fi] = kc;
                    float4 xv = lds_f4(xraddr);
                    if (s == 0) {
                        sts_f4(xaaddr, make_float4(fmaf(cb, kc.x, xv.x), fmaf(cb, kc.y, xv.y),
                                                   fmaf(cb, kc.z, xv.z), fmaf(cb, kc.w, xv.w)));
                    } else if (cb != 0.0f) {
                        float4 t = lds_f4(xaaddr);
                        sts_f4(xaaddr, make_float4(fmaf(cb, kc.x, t.x), fmaf(cb, kc.y, t.y),
                                                   fmaf(cb, kc.z, t.z), fmaf(cb, kc.w, t.w)));
                    }
                    float4 na;
                    if (!fin) {            // y_{s+2} = x + cc*k_cur + sum_{sl<s}
                        na = make_float4(fmaf(cc, kc.x, xv.x), fmaf(cc, kc.y, xv.y),
                                         fmaf(cc, kc.z, xv.z), fmaf(cc, kc.w, xv.w));
                        float4 kv[4];
#pragma unroll
                        for (int sl = 0; sl < 4; sl++)
                            if (sl < s) kv[sl] = *(const float4*)&g_k[sl][fi];
#pragma unroll
                        for (int sl = 0; sl < 4; sl++)
                            if (sl < s) {
                                float cf = c_slot[s][sl];
                                na.x = fmaf(cf, kv[sl].x, na.x);
                                na.y = fmaf(cf, kv[sl].y, na.y);
                                na.z = fmaf(cf, kv[sl].z, na.z);
                                na.w = fmaf(cf, kv[sl].w, na.w);
                            }
                    } else {               // new x = xacc + h*b6*k6
                        float4 t = lds_f4(xaaddr);
                        na = make_float4(fmaf(cc, kc.x, t.x), fmaf(cc, kc.y, t.y),
                                         fmaf(cc, kc.z, t.z), fmaf(cc, kc.w, t.w));
                        sts_f4(xraddr, na);            // new x state
                    }
                    int row = mi * 16 + erow, col = ecol + ni * 8;
                    if (g == NGEMM - 1) {
                        *(float2*)&out[(growb + row) * DIM + col] = make_float2(na.x, na.y);
                        *(float2*)&out[(growb + row + 8) * DIM + col] = make_float2(na.z, na.w);
                    } else {
                        writeA(sb, nbuf, row, col, na.x, na.y);
                        writeA(sb, nbuf, row + 8, col, na.z, na.w);
                    }
                }
        }
        __syncthreads();   // publish A buffer (g+1)&1
    }
}

extern "C" void kernel_launch(void* const* d_in, const int* in_sizes, int n_in,
                              void* d_out, int out_size) {
    (void)in_sizes; (void)n_in; (void)out_size;
    const float* x0 = (const float*)d_in[0];
    const float* W1 = (const float*)d_in[1];
    const float* W2 = (const float*)d_in[2];
    float* out = (float*)d_out;

    prep_kernel<<<512, 256>>>(W1, W2);
    cudaFuncSetAttribute(ode_hmma_kernel,
                         cudaFuncAttributeMaxDynamicSharedMemorySize, SMEM_BYTES);
    ode_hmma_kernel<<<NCTA, THREADS, SMEM_BYTES>>>(x0, out);
}